// round 6
// baseline (speedup 1.0000x reference)
#include <cuda_runtime.h>
#include <cstdint>

#define BB    16384
#define FF    30
#define BINS  30
#define EMB   100
#define NROW  (BB*FF)          // 491520
#define TM    128              // rows per CTA
#define NCTAS (NROW/TM)        // 3840
#define NTHR  256

#define NPAD  104              // 13 n8 tiles
#define AST   104              // A row stride in bf16 (208 B = 13 x 16B)
#define BST   104              // B row stride in bf16
#define SST   108              // stage row stride in floats

#define A_BYTES (TM * AST * 2)      // 26624
#define B_BYTES (NPAD * BST * 2)    // 21632
#define STAGE_BYTES (TM * SST * 4)  // 55296 (overlaps A+B, both dead post-MMA)
#define DYN_SMEM (STAGE_BYTES + 32)

// ---------------- helpers ----------------
__device__ __forceinline__ uint32_t smem_u32(const void* p) {
    uint32_t a;
    asm("{ .reg .u64 t; cvta.to.shared.u64 t, %1; cvt.u32.u64 %0, t; }" : "=r"(a) : "l"(p));
    return a;
}
__device__ __forceinline__ void sts128(uint32_t a, uint4 v) {
    asm volatile("st.shared.v4.b32 [%0], {%1,%2,%3,%4};" :: "r"(a), "r"(v.x), "r"(v.y), "r"(v.z), "r"(v.w) : "memory");
}
__device__ __forceinline__ void sts64f(uint32_t a, float x, float y) {
    asm volatile("st.shared.v2.f32 [%0], {%1,%2};" :: "r"(a), "f"(x), "f"(y) : "memory");
}
__device__ __forceinline__ void sts16(uint32_t a, unsigned short v) {
    asm volatile("st.shared.b16 [%0], %1;" :: "r"(a), "h"(v) : "memory");
}
__device__ __forceinline__ float4 lds128f(uint32_t a) {
    float4 v;
    asm volatile("ld.shared.v4.f32 {%0,%1,%2,%3}, [%4];"
                 : "=f"(v.x), "=f"(v.y), "=f"(v.z), "=f"(v.w) : "r"(a));
    return v;
}
__device__ __forceinline__ void ldm_x4(uint32_t& r0, uint32_t& r1, uint32_t& r2, uint32_t& r3, uint32_t a) {
    asm volatile("ldmatrix.sync.aligned.m8n8.x4.shared.b16 {%0,%1,%2,%3}, [%4];"
                 : "=r"(r0), "=r"(r1), "=r"(r2), "=r"(r3) : "r"(a));
}
__device__ __forceinline__ void ldm_x2(uint32_t& r0, uint32_t& r1, uint32_t a) {
    asm volatile("ldmatrix.sync.aligned.m8n8.x2.shared.b16 {%0,%1}, [%2];"
                 : "=r"(r0), "=r"(r1) : "r"(a));
}
__device__ __forceinline__ void mma_bf16(float& d0, float& d1, float& d2, float& d3,
                                         uint32_t a0, uint32_t a1, uint32_t a2, uint32_t a3,
                                         uint32_t b0, uint32_t b1) {
    asm volatile("mma.sync.aligned.m16n8k16.row.col.f32.bf16.bf16.f32 "
                 "{%0,%1,%2,%3}, {%4,%5,%6,%7}, {%8,%9}, {%0,%1,%2,%3};"
                 : "+f"(d0), "+f"(d1), "+f"(d2), "+f"(d3)
                 : "r"(a0), "r"(a1), "r"(a2), "r"(a3), "r"(b0), "r"(b1));
}
// pack: low half = bf16(lo), high half = bf16(hi)
__device__ __forceinline__ uint32_t pack_bf16x2(float lo, float hi) {
    uint32_t r;
    asm("cvt.rn.bf16x2.f32 %0, %2, %1;" : "=r"(r) : "f"(lo), "f"(hi));
    return r;
}

// ---------------------------------------------------------------------------
// Fused kernel: per CTA rebuild d-coefs + B image, softmax -> A, MMA, store.
// 256 threads, 8 warps; warp w owns rows [16w, 16w+16), full N=104.
// ---------------------------------------------------------------------------
__global__ void __launch_bounds__(NTHR)
main_kernel(const float* __restrict__ x,
            const float* __restrict__ W1,
            const float* __restrict__ Wl,
            const float* __restrict__ W2,
            float* __restrict__ out) {
    extern __shared__ char raw[];
    __shared__ float vs[2][32];
    __shared__ float us[2][32];
    __shared__ float dsh[2][32];

    const int tid  = threadIdx.x;
    const int wid  = tid >> 5;
    const int lane = tid & 31;

    uint32_t base  = smem_u32(raw);         // 16B aligned
    uint32_t abase = base;                  // A tile  [128][104] bf16
    uint32_t bbase = base + A_BYTES;        // B tile  [104][104] bf16
    uint32_t sbase = base;                  // stage   [128][108] f32 (overlaps A+B)

    // ---- build B image (tid<104): W2 row -> bf16 hi/lo split, K-segs [hi|lo|hi]
    if (tid < NPAD) {
        const int n = tid;
        uint32_t brow = bbase + (uint32_t)n * (BST * 2);
        if (n < EMB) {
            #pragma unroll
            for (int o = 0; o < BINS; o++) {
                float w = W2[n * BINS + o];
                uint32_t hp = pack_bf16x2(w, 0.f);
                unsigned short h = (unsigned short)(hp & 0xFFFF);
                float hf = __uint_as_float(((uint32_t)h) << 16);
                uint32_t lp = pack_bf16x2(w - hf, 0.f);
                sts16(brow + (uint32_t)(2 * o), h);
                sts16(brow + (uint32_t)(2 * (o + 32)), (unsigned short)(lp & 0xFFFF));
                sts16(brow + (uint32_t)(2 * (o + 64)), h);
            }
            // zero pad cols 30,31 / 62,63 / 94..103
            sts16(brow + 60, 0); sts16(brow + 62, 0);
            sts16(brow + 124, 0); sts16(brow + 126, 0);
            #pragma unroll
            for (int c = 94; c < BST; c++) sts16(brow + 2 * c, 0);
        } else {
            for (int c = 0; c < BST; c += 8) {
                uint4 z = make_uint4(0, 0, 0, 0);
                sts128(brow + 2 * c, z);
            }
        }
    }

    // ---- d-coefficient chain on threads 128..191 (warps 4,5) ----
    if (tid >= 128 && tid < 192) {
        int s = (tid - 128) >> 5, o = (tid - 128) & 31;
        float v = 0.f;
        if (o < BINS) {
            float w = W1[o];
            bool act = (s == 0) ? (w > 0.f) : (w < 0.f);
            v = act ? w : 0.01f * w;
        }
        vs[s][o] = v;
    }
    __syncthreads();
    if (tid >= 128 && tid < 192) {
        int s = (tid - 128) >> 5, o = (tid - 128) & 31;
        float u = 0.f;
        if (o < BINS) {
            #pragma unroll
            for (int i = 0; i < BINS; i++) u += Wl[o * BINS + i] * vs[s][i];
            u += 0.1f * vs[s][o];
        }
        us[s][o] = u;
    }
    __syncthreads();
    if (tid >= 128 && tid < 192) {
        int s = (tid - 128) >> 5, o = (tid - 128) & 31;
        float dval = 0.f;
        if (o < BINS) {
            float u = us[s][o];
            float ext = us[s][0];
            #pragma unroll
            for (int i = 1; i < BINS; i++) {
                float z = us[s][i];
                ext = (s == 0) ? fmaxf(ext, z) : fminf(ext, z);
            }
            const float T_LOG2E = 0.5f * 1.44269504088896340736f;
            dval = T_LOG2E * (u - ext);
        }
        dsh[s][o] = dval;
    }
    __syncthreads();

    // ---- per-row softmax (tid<128): p_o = exp2(x*d[o]) * invZ, hi/lo split -> A
    if (tid < TM) {
        const int row = blockIdx.x * TM + tid;
        const float xv = x[row];
        const float* d = (xv > 0.f) ? dsh[0] : dsh[1];

        float p[BINS];
        float Z = 0.f;
        #pragma unroll
        for (int o = 0; o < BINS; o++) {
            float a = xv * d[o];
            float e;
            asm("ex2.approx.ftz.f32 %0, %1;" : "=f"(e) : "f"(a));
            p[o] = e;
            Z += e;
        }
        const float invZ = 1.0f / Z;

        uint32_t arow[52];
        #pragma unroll
        for (int i = 0; i < 52; i++) arow[i] = 0u;
        #pragma unroll
        for (int k = 0; k < 15; k++) {
            float p0 = p[2 * k] * invZ;
            float p1 = p[2 * k + 1] * invZ;
            uint32_t hp = pack_bf16x2(p0, p1);
            float h0 = __uint_as_float(hp << 16);
            float h1 = __uint_as_float(hp & 0xFFFF0000u);
            uint32_t lp = pack_bf16x2(p0 - h0, p1 - h1);
            arow[k]      = hp;     // cols  0..29 : p_hi
            arow[16 + k] = hp;     // cols 32..61 : p_hi
            arow[32 + k] = lp;     // cols 64..93 : p_lo
        }
        uint32_t ra = abase + (uint32_t)tid * (AST * 2);
        #pragma unroll
        for (int i = 0; i < 13; i++) {
            uint4 v = make_uint4(arow[4 * i], arow[4 * i + 1], arow[4 * i + 2], arow[4 * i + 3]);
            sts128(ra + i * 16u, v);
        }
    }
    __syncthreads();

    // ---- MMA mainloop: per warp M=16 (1 m16), N=104 (13 n8), K=96 (6 k16) ----
    float acc[13][4];
    #pragma unroll
    for (int nj = 0; nj < 13; nj++)
        #pragma unroll
        for (int q = 0; q < 4; q++) acc[nj][q] = 0.f;

    // A frag addressing: lanes 0-15 rows, lanes 16-31 same rows +16B chunk
    const uint32_t a_addr0 = abase + (uint32_t)((16 * wid + (lane & 15)) * (AST * 2) + (lane >> 4) * 16);
    // B x4 addressing: g=lane>>3: n_tile = pair*2 + (g>>1), chunk = g&1
    const int bg = lane >> 3;
    const uint32_t b_addr0 = bbase + (uint32_t)((8 * (bg >> 1) + (lane & 7)) * (BST * 2) + (bg & 1) * 16);
    // B x2 tail (nj=12): lanes 0-7 chunk0, 8-15 chunk1
    const uint32_t bt_addr0 = bbase + (uint32_t)((96 + (lane & 7)) * (BST * 2) + ((lane >> 3) & 1) * 16);

    #pragma unroll
    for (int kk = 0; kk < 6; kk++) {
        uint32_t a0, a1, a2, a3;
        ldm_x4(a0, a1, a2, a3, a_addr0 + kk * 32u);
        #pragma unroll
        for (int pr = 0; pr < 6; pr++) {
            uint32_t b0, b1, b2, b3;
            ldm_x4(b0, b1, b2, b3, b_addr0 + (uint32_t)(pr * 16 * (BST * 2)) + kk * 32u);
            int nj = 2 * pr;
            mma_bf16(acc[nj][0], acc[nj][1], acc[nj][2], acc[nj][3], a0, a1, a2, a3, b0, b1);
            mma_bf16(acc[nj+1][0], acc[nj+1][1], acc[nj+1][2], acc[nj+1][3], a0, a1, a2, a3, b2, b3);
        }
        {
            uint32_t b0, b1;
            ldm_x2(b0, b1, bt_addr0 + kk * 32u);
            mma_bf16(acc[12][0], acc[12][1], acc[12][2], acc[12][3], a0, a1, a2, a3, b0, b1);
        }
    }
    __syncthreads();   // A/B dead; stage may overwrite

    // ---- stage fragments to smem (f32, [128][SST]) ----
    {
        const int rr = lane >> 2;            // 0..7
        const int cc = 2 * (lane & 3);       // 0,2,4,6
        const int r0 = 16 * wid + rr;
        #pragma unroll
        for (int nj = 0; nj < 13; nj++) {
            const int c0 = 8 * nj + cc;
            uint32_t sa = sbase + (uint32_t)((r0 * SST + c0) * 4);
            sts64f(sa, acc[nj][0], acc[nj][1]);
            sts64f(sa + 8u * SST * 4u, acc[nj][2], acc[nj][3]);
        }
    }
    __syncthreads();

    // ---- cooperative coalesced store: 128 rows x 100 cols = 3200 float4 ----
    float* outb = out + (size_t)blockIdx.x * TM * EMB;
    #pragma unroll
    for (int it = 0; it < 13; it++) {
        int q = tid + it * NTHR;
        if (q < 3200) {
            int rr = q / 25, c = q % 25;
            float4 v = lds128f(sbase + (uint32_t)((rr * SST + 4 * c) * 4));
            *reinterpret_cast<float4*>(outb + (size_t)rr * EMB + 4 * c) = v;
        }
    }
}

// ---------------------------------------------------------------------------
extern "C" void kernel_launch(void* const* d_in, const int* in_sizes, int n_in,
                              void* d_out, int out_size) {
    const float* x  = (const float*)d_in[0];   // (16384, 1, 30)
    const float* W1 = (const float*)d_in[1];   // (30, 1)
    const float* Wl = (const float*)d_in[2];   // (30, 30)
    const float* W2 = (const float*)d_in[3];   // (100, 30)
    float* out = (float*)d_out;                // (16384, 3000)

    cudaFuncSetAttribute(main_kernel, cudaFuncAttributeMaxDynamicSharedMemorySize, DYN_SMEM);
    main_kernel<<<NCTAS, NTHR, DYN_SMEM>>>(x, W1, Wl, W2, out);
}

// round 7
// speedup vs baseline: 1.1120x; 1.1120x over previous
#include <cuda_runtime.h>
#include <cstdint>

#define BB    16384
#define FF    30
#define BINS  30
#define EMB   100
#define NROW  (BB*FF)          // 491520
#define TM    128              // rows per CTA
#define NCTAS (NROW/TM)        // 3840
#define NTHR  256

#define NPAD  104              // 13 n8 tiles
#define AST   104              // A row stride in bf16 (208 B = 13 x 16B)
#define BST   104              // B row stride in bf16

#define A_BYTES (TM * AST * 2)      // 26624
#define B_BYTES (NPAD * BST * 2)    // 21632
#define DYN_SMEM (A_BYTES + B_BYTES + 32)   // 48288

// ---------------- helpers ----------------
__device__ __forceinline__ uint32_t smem_u32(const void* p) {
    uint32_t a;
    asm("{ .reg .u64 t; cvta.to.shared.u64 t, %1; cvt.u32.u64 %0, t; }" : "=r"(a) : "l"(p));
    return a;
}
__device__ __forceinline__ void sts128(uint32_t a, uint4 v) {
    asm volatile("st.shared.v4.b32 [%0], {%1,%2,%3,%4};" :: "r"(a), "r"(v.x), "r"(v.y), "r"(v.z), "r"(v.w) : "memory");
}
__device__ __forceinline__ void ldm_x4(uint32_t& r0, uint32_t& r1, uint32_t& r2, uint32_t& r3, uint32_t a) {
    asm volatile("ldmatrix.sync.aligned.m8n8.x4.shared.b16 {%0,%1,%2,%3}, [%4];"
                 : "=r"(r0), "=r"(r1), "=r"(r2), "=r"(r3) : "r"(a));
}
__device__ __forceinline__ void ldm_x2(uint32_t& r0, uint32_t& r1, uint32_t a) {
    asm volatile("ldmatrix.sync.aligned.m8n8.x2.shared.b16 {%0,%1}, [%2];"
                 : "=r"(r0), "=r"(r1) : "r"(a));
}
__device__ __forceinline__ void mma_bf16(float& d0, float& d1, float& d2, float& d3,
                                         uint32_t a0, uint32_t a1, uint32_t a2, uint32_t a3,
                                         uint32_t b0, uint32_t b1) {
    asm volatile("mma.sync.aligned.m16n8k16.row.col.f32.bf16.bf16.f32 "
                 "{%0,%1,%2,%3}, {%4,%5,%6,%7}, {%8,%9}, {%0,%1,%2,%3};"
                 : "+f"(d0), "+f"(d1), "+f"(d2), "+f"(d3)
                 : "r"(a0), "r"(a1), "r"(a2), "r"(a3), "r"(b0), "r"(b1));
}
// pack: low half = bf16(lo), high half = bf16(hi)
__device__ __forceinline__ uint32_t pack_bf16x2(float lo, float hi) {
    uint32_t r;
    asm("cvt.rn.bf16x2.f32 %0, %2, %1;" : "=r"(r) : "f"(lo), "f"(hi));
    return r;
}

// ---------------- device globals ----------------
__device__ float g_d[2][32];                                 // exp2 coefficients per sign
__device__ __align__(16) unsigned short g_B2[NPAD * BST];    // Bt image: [n][k] bf16, MMA-ready

// ---------------------------------------------------------------------------
// Precompute (tiny, 1 block): g_d from W1/Wl; g_B2 = W2 hi/lo split,
// K-segments [w_hi | w_lo | w_hi], rows n>=100 zero.
// ---------------------------------------------------------------------------
__global__ void precompute_kernel(const float* __restrict__ W1,
                                  const float* __restrict__ Wl,
                                  const float* __restrict__ W2) {
    __shared__ float vs[2][32];
    __shared__ float us[2][32];
    int t = threadIdx.x;       // 128 threads

    if (t < 64) {
        int s = t >> 5, o = t & 31;
        float v = 0.f;
        if (o < BINS) {
            float w = W1[o];
            bool act = (s == 0) ? (w > 0.f) : (w < 0.f);
            v = act ? w : 0.01f * w;
        }
        vs[s][o] = v;
    }
    __syncthreads();
    if (t < 64) {
        int s = t >> 5, o = t & 31;
        float u = 0.f;
        if (o < BINS) {
            #pragma unroll
            for (int i = 0; i < BINS; i++) u += Wl[o * BINS + i] * vs[s][i];
            u += 0.1f * vs[s][o];
        }
        us[s][o] = u;
    }
    __syncthreads();
    if (t < 64) {
        int s = t >> 5, o = t & 31;
        float dval = 0.f;
        if (o < BINS) {
            float u = us[s][o];
            float ext = us[s][0];
            #pragma unroll
            for (int i = 1; i < BINS; i++) {
                float z = us[s][i];
                ext = (s == 0) ? fmaxf(ext, z) : fminf(ext, z);
            }
            const float T_LOG2E = 0.5f * 1.44269504088896340736f;
            dval = T_LOG2E * (u - ext);
        }
        g_d[s][o] = dval;
    }

    if (t < NPAD) {
        int n = t;
        unsigned short hb[BINS], lb[BINS];
        if (n < EMB) {
            #pragma unroll
            for (int o = 0; o < BINS; o++) {
                float w = W2[n * BINS + o];
                uint32_t hp = pack_bf16x2(w, 0.f);
                unsigned short h = (unsigned short)(hp & 0xFFFF);
                float hf = __uint_as_float(((uint32_t)h) << 16);
                uint32_t lp = pack_bf16x2(w - hf, 0.f);
                hb[o] = h;
                lb[o] = (unsigned short)(lp & 0xFFFF);
            }
        } else {
            #pragma unroll
            for (int o = 0; o < BINS; o++) { hb[o] = 0; lb[o] = 0; }
        }
        for (int c = 0; c < BST; c++) {
            unsigned short bits = 0;
            if (c < 30)                 bits = hb[c];
            else if (c >= 32 && c < 62) bits = lb[c - 32];
            else if (c >= 64 && c < 94) bits = hb[c - 64];
            g_B2[n * BST + c] = bits;
        }
    }
}

// ---------------------------------------------------------------------------
// Main kernel: 128 rows/CTA, 256 threads / 8 warps; warp w = m16 tile w,
// full N=104, K=96. Direct fragment stores (no stage).
// ---------------------------------------------------------------------------
__global__ void __launch_bounds__(NTHR, 3)
main_kernel(const float* __restrict__ x,
            float* __restrict__ out) {
    extern __shared__ char raw[];
    __shared__ float dsh[2][32];

    const int tid  = threadIdx.x;
    const int wid  = tid >> 5;
    const int lane = tid & 31;

    uint32_t base  = smem_u32(raw);         // 16B aligned
    uint32_t abase = base;                  // A tile  [128][104] bf16
    uint32_t bbase = base + A_BYTES;        // B tile  [104][104] bf16

    if (tid < 64) dsh[tid >> 5][tid & 31] = g_d[tid >> 5][tid & 31];
    // coalesced copy of MMA-ready B image (1352 uint4)
    {
        const uint4* gb = reinterpret_cast<const uint4*>(g_B2);
        for (int i = tid; i < B_BYTES / 16; i += NTHR) sts128(bbase + (uint32_t)i * 16u, gb[i]);
    }
    __syncthreads();

    // ---- per-row softmax (tid<128): p_o = exp2(x*d[o]) * invZ, hi/lo split -> A
    if (tid < TM) {
        const int row = blockIdx.x * TM + tid;
        const float xv = x[row];
        const float* d = (xv > 0.f) ? dsh[0] : dsh[1];

        float p[BINS];
        float Z = 0.f;
        #pragma unroll
        for (int o = 0; o < BINS; o++) {
            float a = xv * d[o];
            float e;
            asm("ex2.approx.ftz.f32 %0, %1;" : "=f"(e) : "f"(a));
            p[o] = e;
            Z += e;
        }
        const float invZ = 1.0f / Z;

        uint32_t arow[52];
        #pragma unroll
        for (int i = 0; i < 52; i++) arow[i] = 0u;
        #pragma unroll
        for (int k = 0; k < 15; k++) {
            float p0 = p[2 * k] * invZ;
            float p1 = p[2 * k + 1] * invZ;
            uint32_t hp = pack_bf16x2(p0, p1);
            float h0 = __uint_as_float(hp << 16);
            float h1 = __uint_as_float(hp & 0xFFFF0000u);
            uint32_t lp = pack_bf16x2(p0 - h0, p1 - h1);
            arow[k]      = hp;     // cols  0..29 : p_hi
            arow[16 + k] = hp;     // cols 32..61 : p_hi
            arow[32 + k] = lp;     // cols 64..93 : p_lo
        }
        uint32_t ra = abase + (uint32_t)tid * (AST * 2);
        #pragma unroll
        for (int i = 0; i < 13; i++) {
            uint4 v = make_uint4(arow[4 * i], arow[4 * i + 1], arow[4 * i + 2], arow[4 * i + 3]);
            sts128(ra + i * 16u, v);
        }
    }
    __syncthreads();

    // ---- MMA mainloop: per warp M=16 (1 m16), N=104 (13 n8), K=96 (6 k16) ----
    float acc[13][4];
    #pragma unroll
    for (int nj = 0; nj < 13; nj++)
        #pragma unroll
        for (int q = 0; q < 4; q++) acc[nj][q] = 0.f;

    const uint32_t a_addr0 = abase + (uint32_t)((16 * wid + (lane & 15)) * (AST * 2) + (lane >> 4) * 16);
    const int bg = lane >> 3;
    const uint32_t b_addr0 = bbase + (uint32_t)((8 * (bg >> 1) + (lane & 7)) * (BST * 2) + (bg & 1) * 16);
    const uint32_t bt_addr0 = bbase + (uint32_t)((96 + (lane & 7)) * (BST * 2) + ((lane >> 3) & 1) * 16);

    #pragma unroll
    for (int kk = 0; kk < 6; kk++) {
        uint32_t a0, a1, a2, a3;
        ldm_x4(a0, a1, a2, a3, a_addr0 + kk * 32u);
        #pragma unroll
        for (int pr = 0; pr < 6; pr++) {
            uint32_t b0, b1, b2, b3;
            ldm_x4(b0, b1, b2, b3, b_addr0 + (uint32_t)(pr * 16 * (BST * 2)) + kk * 32u);
            int nj = 2 * pr;
            mma_bf16(acc[nj][0], acc[nj][1], acc[nj][2], acc[nj][3], a0, a1, a2, a3, b0, b1);
            mma_bf16(acc[nj+1][0], acc[nj+1][1], acc[nj+1][2], acc[nj+1][3], a0, a1, a2, a3, b2, b3);
        }
        {
            uint32_t b0, b1;
            ldm_x2(b0, b1, bt_addr0 + kk * 32u);
            mma_bf16(acc[12][0], acc[12][1], acc[12][2], acc[12][3], a0, a1, a2, a3, b0, b1);
        }
    }

    // ---- direct fragment stores: quads of lanes write packed 32B sectors ----
    {
        float* outb = out + (size_t)blockIdx.x * TM * EMB;
        const int r0 = 16 * wid + (lane >> 2);
        const int cb = 2 * (lane & 3);
        float* row0 = outb + (size_t)r0 * EMB;
        float* row1 = outb + (size_t)(r0 + 8) * EMB;
        #pragma unroll
        for (int nj = 0; nj < 12; nj++) {
            const int c = 8 * nj + cb;
            float2 v0; v0.x = acc[nj][0]; v0.y = acc[nj][1];
            float2 v1; v1.x = acc[nj][2]; v1.y = acc[nj][3];
            *reinterpret_cast<float2*>(row0 + c) = v0;
            *reinterpret_cast<float2*>(row1 + c) = v1;
        }
        if (cb < 4) {   // cols 96..99 only
            const int c = 96 + cb;
            float2 v0; v0.x = acc[12][0]; v0.y = acc[12][1];
            float2 v1; v1.x = acc[12][2]; v1.y = acc[12][3];
            *reinterpret_cast<float2*>(row0 + c) = v0;
            *reinterpret_cast<float2*>(row1 + c) = v1;
        }
    }
}

// ---------------------------------------------------------------------------
extern "C" void kernel_launch(void* const* d_in, const int* in_sizes, int n_in,
                              void* d_out, int out_size) {
    const float* x  = (const float*)d_in[0];   // (16384, 1, 30)
    const float* W1 = (const float*)d_in[1];   // (30, 1)
    const float* Wl = (const float*)d_in[2];   // (30, 30)
    const float* W2 = (const float*)d_in[3];   // (100, 30)
    float* out = (float*)d_out;                // (16384, 3000)

    cudaFuncSetAttribute(main_kernel, cudaFuncAttributeMaxDynamicSharedMemorySize, DYN_SMEM);
    precompute_kernel<<<1, 128>>>(W1, Wl, W2);
    main_kernel<<<NCTAS, NTHR, DYN_SMEM>>>(x, out);
}

// round 9
// speedup vs baseline: 1.6225x; 1.4592x over previous
#include <cuda_runtime.h>
#include <cstdint>

#define BB    16384
#define FF    30
#define BINS  30
#define EMB   100
#define NROW  (BB*FF)          // 491520
#define TM    128              // rows per tile
#define NTILES (NROW/TM)       // 3840
#define NTHR  256
#define GRID  456              // 152 SMs x 3 CTAs (GB300)

#define NPAD  104              // 13 n8 tiles
#define AST   104              // A row stride in bf16 (208 B = 13 x 16B)
#define BST   104              // B row stride in bf16

#define A_BYTES (TM * AST * 2)      // 26624
#define B_BYTES (NPAD * BST * 2)    // 21632
#define DYN_SMEM (2*A_BYTES + B_BYTES + 32)   // 74912

// ---------------- helpers ----------------
__device__ __forceinline__ uint32_t smem_u32(const void* p) {
    uint32_t a;
    asm("{ .reg .u64 t; cvta.to.shared.u64 t, %1; cvt.u32.u64 %0, t; }" : "=r"(a) : "l"(p));
    return a;
}
__device__ __forceinline__ void sts128(uint32_t a, uint4 v) {
    asm volatile("st.shared.v4.b32 [%0], {%1,%2,%3,%4};" :: "r"(a), "r"(v.x), "r"(v.y), "r"(v.z), "r"(v.w) : "memory");
}
__device__ __forceinline__ void sts16(uint32_t a, unsigned short v) {
    asm volatile("st.shared.b16 [%0], %1;" :: "r"(a), "h"(v) : "memory");
}
__device__ __forceinline__ void ldm_x4(uint32_t& r0, uint32_t& r1, uint32_t& r2, uint32_t& r3, uint32_t a) {
    asm volatile("ldmatrix.sync.aligned.m8n8.x4.shared.b16 {%0,%1,%2,%3}, [%4];"
                 : "=r"(r0), "=r"(r1), "=r"(r2), "=r"(r3) : "r"(a));
}
__device__ __forceinline__ void ldm_x2(uint32_t& r0, uint32_t& r1, uint32_t a) {
    asm volatile("ldmatrix.sync.aligned.m8n8.x2.shared.b16 {%0,%1}, [%2];"
                 : "=r"(r0), "=r"(r1) : "r"(a));
}
__device__ __forceinline__ void mma_bf16(float& d0, float& d1, float& d2, float& d3,
                                         uint32_t a0, uint32_t a1, uint32_t a2, uint32_t a3,
                                         uint32_t b0, uint32_t b1) {
    asm volatile("mma.sync.aligned.m16n8k16.row.col.f32.bf16.bf16.f32 "
                 "{%0,%1,%2,%3}, {%4,%5,%6,%7}, {%8,%9}, {%0,%1,%2,%3};"
                 : "+f"(d0), "+f"(d1), "+f"(d2), "+f"(d3)
                 : "r"(a0), "r"(a1), "r"(a2), "r"(a3), "r"(b0), "r"(b1));
}
// pack: low half = bf16(lo), high half = bf16(hi)
__device__ __forceinline__ uint32_t pack_bf16x2(float lo, float hi) {
    uint32_t r;
    asm("cvt.rn.bf16x2.f32 %0, %2, %1;" : "=r"(r) : "f"(lo), "f"(hi));
    return r;
}

// ---------------------------------------------------------------------------
// Persistent fused kernel. Init once per CTA: d-coefs (warps 0-1, shuffle,
// all-lane-convergent collectives), B image (threads 64..167). Tile loop:
// softmax -> A[buf] -> 1 sync -> MMA -> direct fragment STG. Double-buffered
// A; x prefetched a tile ahead.
// ---------------------------------------------------------------------------
__global__ void __launch_bounds__(NTHR, 3)
main_kernel(const float* __restrict__ x,
            const float* __restrict__ W1,
            const float* __restrict__ Wl,
            const float* __restrict__ W2,
            float* __restrict__ out) {
    extern __shared__ char raw[];
    __shared__ float dsh[2][32];

    const int tid  = threadIdx.x;
    const int wid  = tid >> 5;
    const int lane = tid & 31;

    uint32_t base  = smem_u32(raw);               // 16B aligned
    uint32_t abase = base;                        // A tiles: 2 x [128][104] bf16
    uint32_t bbase = base + 2 * A_BYTES;          // B tile  [104][104] bf16

    // ---- init: d-coefficients, warps 0 (x>0) and 1 (x<0) ----
    // ALL warp-collectives executed by all 32 lanes (no divergent shfl_sync).
    if (wid < 2) {
        const int s = wid, o = lane;
        float v = 0.f;
        if (o < BINS) {
            float w = W1[o];
            bool act = (s == 0) ? (w > 0.f) : (w < 0.f);
            v = act ? w : 0.01f * w;
        }
        float u = 0.f;
        #pragma unroll
        for (int i = 0; i < BINS; i++) {
            float vi = __shfl_sync(0xFFFFFFFFu, v, i);       // convergent
            float wv = (o < BINS) ? Wl[o * BINS + i] : 0.f;  // guarded load
            u += wv * vi;
        }
        u += 0.1f * v;
        float ured = (o < BINS) ? u : ((s == 0) ? -3.0e38f : 3.0e38f);
        #pragma unroll
        for (int off = 16; off > 0; off >>= 1) {
            float t2 = __shfl_xor_sync(0xFFFFFFFFu, ured, off);  // convergent
            ured = (s == 0) ? fmaxf(ured, t2) : fminf(ured, t2);
        }
        const float T_LOG2E = 0.5f * 1.44269504088896340736f;
        dsh[s][o] = (o < BINS) ? T_LOG2E * (u - ured) : 0.f;
    }

    // ---- init: B image rows (threads 64..167), K-segs [w_hi|w_lo|w_hi] ----
    if (tid >= 64 && tid < 64 + NPAD) {
        const int n = tid - 64;
        uint32_t brow = bbase + (uint32_t)n * (BST * 2);
        if (n < EMB) {
            #pragma unroll
            for (int o = 0; o < BINS; o++) {
                float w = W2[n * BINS + o];
                uint32_t hp = pack_bf16x2(w, 0.f);
                unsigned short h = (unsigned short)(hp & 0xFFFF);
                float hf = __uint_as_float(((uint32_t)h) << 16);
                uint32_t lp = pack_bf16x2(w - hf, 0.f);
                sts16(brow + (uint32_t)(2 * o), h);
                sts16(brow + (uint32_t)(2 * (o + 32)), (unsigned short)(lp & 0xFFFF));
                sts16(brow + (uint32_t)(2 * (o + 64)), h);
            }
            sts16(brow + 60, 0);  sts16(brow + 62, 0);     // cols 30,31
            sts16(brow + 124, 0); sts16(brow + 126, 0);    // cols 62,63
            #pragma unroll
            for (int c = 94; c < BST; c++) sts16(brow + 2 * c, 0);
        } else {
            uint4 z = make_uint4(0, 0, 0, 0);
            for (int c = 0; c < BST; c += 8) sts128(brow + 2 * c, z);
        }
    }
    __syncthreads();

    // MMA addressing constants (per-warp)
    const int bg = lane >> 3;
    const uint32_t b_addr0 = bbase + (uint32_t)((8 * (bg >> 1) + (lane & 7)) * (BST * 2) + (bg & 1) * 16);
    const uint32_t bt_addr0 = bbase + (uint32_t)((96 + (lane & 7)) * (BST * 2) + ((lane >> 3) & 1) * 16);
    const uint32_t a_off0 = (uint32_t)((16 * wid + (lane & 15)) * (AST * 2) + (lane >> 4) * 16);

    // ---- tile loop (trip count uniform per CTA: tile = bid + k*GRID) ----
    int tile = blockIdx.x;
    float xv = (tid < TM && tile < NTILES) ? x[(size_t)tile * TM + tid] : 0.f;
    int buf = 0;

    for (; tile < NTILES; tile += GRID, buf ^= 1) {
        // prefetch next tile's x
        const int ntile = tile + GRID;
        float xv_next = 0.f;
        if (tid < TM && ntile < NTILES) xv_next = x[(size_t)ntile * TM + tid];

        const uint32_t abuf = abase + (uint32_t)buf * A_BYTES;

        // softmax + A build (threads 0..127)
        if (tid < TM) {
            const float* d = (xv > 0.f) ? dsh[0] : dsh[1];
            float p[BINS];
            float Z = 0.f;
            #pragma unroll
            for (int o = 0; o < BINS; o++) {
                float a = xv * d[o];
                float e;
                asm("ex2.approx.ftz.f32 %0, %1;" : "=f"(e) : "f"(a));
                p[o] = e;
                Z += e;
            }
            float invZ;
            asm("rcp.approx.ftz.f32 %0, %1;" : "=f"(invZ) : "f"(Z));

            uint32_t arow[52];
            #pragma unroll
            for (int i = 0; i < 52; i++) arow[i] = 0u;
            #pragma unroll
            for (int k = 0; k < 15; k++) {
                float p0 = p[2 * k] * invZ;
                float p1 = p[2 * k + 1] * invZ;
                uint32_t hp = pack_bf16x2(p0, p1);
                float h0 = __uint_as_float(hp << 16);
                float h1 = __uint_as_float(hp & 0xFFFF0000u);
                uint32_t lp = pack_bf16x2(p0 - h0, p1 - h1);
                arow[k]      = hp;     // cols  0..29 : p_hi
                arow[16 + k] = hp;     // cols 32..61 : p_hi
                arow[32 + k] = lp;     // cols 64..93 : p_lo
            }
            uint32_t ra = abuf + (uint32_t)tid * (AST * 2);
            #pragma unroll
            for (int i = 0; i < 13; i++) {
                uint4 v = make_uint4(arow[4 * i], arow[4 * i + 1], arow[4 * i + 2], arow[4 * i + 3]);
                sts128(ra + i * 16u, v);
            }
        }
        __syncthreads();   // the only barrier per tile

        // MMA: per warp M=16, N=104 (13 n8), K=96 (6 k16)
        float acc[13][4];
        #pragma unroll
        for (int nj = 0; nj < 13; nj++)
            #pragma unroll
            for (int q = 0; q < 4; q++) acc[nj][q] = 0.f;

        const uint32_t a_addr0 = abuf + a_off0;
        #pragma unroll
        for (int kk = 0; kk < 6; kk++) {
            uint32_t a0, a1, a2, a3;
            ldm_x4(a0, a1, a2, a3, a_addr0 + kk * 32u);
            #pragma unroll
            for (int pr = 0; pr < 6; pr++) {
                uint32_t b0, b1, b2, b3;
                ldm_x4(b0, b1, b2, b3, b_addr0 + (uint32_t)(pr * 16 * (BST * 2)) + kk * 32u);
                int nj = 2 * pr;
                mma_bf16(acc[nj][0], acc[nj][1], acc[nj][2], acc[nj][3], a0, a1, a2, a3, b0, b1);
                mma_bf16(acc[nj+1][0], acc[nj+1][1], acc[nj+1][2], acc[nj+1][3], a0, a1, a2, a3, b2, b3);
            }
            {
                uint32_t b0, b1;
                ldm_x2(b0, b1, bt_addr0 + kk * 32u);
                mma_bf16(acc[12][0], acc[12][1], acc[12][2], acc[12][3], a0, a1, a2, a3, b0, b1);
            }
        }

        // direct fragment stores (quads write packed 32B sectors)
        {
            float* outb = out + (size_t)tile * TM * EMB;
            const int r0 = 16 * wid + (lane >> 2);
            const int cb = 2 * (lane & 3);
            float* row0 = outb + (size_t)r0 * EMB;
            float* row1 = outb + (size_t)(r0 + 8) * EMB;
            #pragma unroll
            for (int nj = 0; nj < 12; nj++) {
                const int c = 8 * nj + cb;
                float2 v0; v0.x = acc[nj][0]; v0.y = acc[nj][1];
                float2 v1; v1.x = acc[nj][2]; v1.y = acc[nj][3];
                *reinterpret_cast<float2*>(row0 + c) = v0;
                *reinterpret_cast<float2*>(row1 + c) = v1;
            }
            if (cb < 4) {   // cols 96..99
                const int c = 96 + cb;
                float2 v0; v0.x = acc[12][0]; v0.y = acc[12][1];
                float2 v1; v1.x = acc[12][2]; v1.y = acc[12][3];
                *reinterpret_cast<float2*>(row0 + c) = v0;
                *reinterpret_cast<float2*>(row1 + c) = v1;
            }
        }

        xv = xv_next;
    }
}

// ---------------------------------------------------------------------------
extern "C" void kernel_launch(void* const* d_in, const int* in_sizes, int n_in,
                              void* d_out, int out_size) {
    const float* x  = (const float*)d_in[0];   // (16384, 1, 30)
    const float* W1 = (const float*)d_in[1];   // (30, 1)
    const float* Wl = (const float*)d_in[2];   // (30, 30)
    const float* W2 = (const float*)d_in[3];   // (100, 30)
    float* out = (float*)d_out;                // (16384, 3000)

    cudaFuncSetAttribute(main_kernel, cudaFuncAttributeMaxDynamicSharedMemorySize, DYN_SMEM);
    main_kernel<<<GRID, NTHR, DYN_SMEM>>>(x, W1, Wl, W2, out);
}